// round 1
// baseline (speedup 1.0000x reference)
#include <cuda_runtime.h>
#include <cuda_bf16.h>
#include <cstdint>

// ---------------- problem constants ----------------
#define HH   2048
#define VV   32000
#define SS   2048
#define BB   2
#define TMm  1024
#define NSEGc 16
#define NTOK 6144          // 4096 main tokens + 2048 math tokens
#define NVC  25            // V chunks
#define NT_PER_CTA 10      // 128-wide N-tiles per chunk (25*10*128 = 32000)
#define VCHUNK 1280
#define LDA 72             // smem row stride in bf16 (144 bytes -> conflict-free LDSM)

// ---------------- scratch (device globals; no allocs allowed) ----------------
__device__ __align__(16) __nv_bfloat16 g_Wbf[(size_t)VV * HH];          // 131 MB
__device__ __align__(16) __nv_bfloat16 g_hid[(size_t)BB * SS * HH];     // 16.8 MB
__device__ __align__(16) __nv_bfloat16 g_Abf[(size_t)NSEGc * HH * 256]; // 16.8 MB
__device__ __align__(16) __nv_bfloat16 g_Bbf[(size_t)NSEGc * 256 * HH]; // 16.8 MB
__device__ __align__(16) __nv_bfloat16 g_inter[(size_t)NSEGc * 128 * 256];
__device__ __align__(16) __nv_bfloat16 g_trans[(size_t)BB * TMm * HH];  // 8.4 MB
__device__ float g_pm[NVC * NTOK];
__device__ float g_ps[NVC * NTOK];
__device__ float g_ld[NTOK];

// ---------------- helpers ----------------
__device__ __forceinline__ uint32_t smem_u32(const void* p) {
    return (uint32_t)__cvta_generic_to_shared(p);
}
__device__ __forceinline__ void ldsm4(uint32_t* r, uint32_t a) {
    asm volatile("ldmatrix.sync.aligned.m8n8.x4.shared.b16 {%0,%1,%2,%3}, [%4];"
                 : "=r"(r[0]), "=r"(r[1]), "=r"(r[2]), "=r"(r[3]) : "r"(a));
}
__device__ __forceinline__ void mma_bf16(float* d, const uint32_t* a, const uint32_t* b) {
    asm volatile(
        "mma.sync.aligned.m16n8k16.row.col.f32.bf16.bf16.f32 "
        "{%0,%1,%2,%3},{%4,%5,%6,%7},{%8,%9},{%0,%1,%2,%3};"
        : "+f"(d[0]), "+f"(d[1]), "+f"(d[2]), "+f"(d[3])
        : "r"(a[0]), "r"(a[1]), "r"(a[2]), "r"(a[3]), "r"(b[0]), "r"(b[1]));
}

// One K_TILE=64 slab: warp computes 16 rows x 128 cols using ldmatrix + mma.
// A fragment from sA (rows m_base..m_base+15), B fragments from sB (128 n-rows).
__device__ __forceinline__ void mma_ktile(float acc[16][4], const __nv_bfloat16* sA,
                                          const __nv_bfloat16* sB, int lane, int mbase) {
#pragma unroll
    for (int kk = 0; kk < 64; kk += 16) {
        uint32_t a[4];
        ldsm4(a, smem_u32(sA + (mbase + (lane & 15)) * LDA + kk + ((lane >> 4) << 3)));
#pragma unroll
        for (int jp = 0; jp < 8; jp++) {
            uint32_t b[4];
            ldsm4(b, smem_u32(sB + ((jp * 2 + (lane >> 4)) * 8 + (lane & 7)) * LDA
                              + kk + (((lane >> 3) & 1) << 3)));
            mma_bf16(acc[2 * jp], a, b);
            mma_bf16(acc[2 * jp + 1], a, b + 2);
        }
    }
}

// Load a 128-row x 64-col bf16 tile into padded smem (256 threads).
__device__ __forceinline__ void load_tile128(__nv_bfloat16* s, const __nv_bfloat16* g,
                                             int ldg, int tid) {
#pragma unroll
    for (int i = 0; i < 4; i++) {
        int idx = tid + i * 256;
        int row = idx >> 3, c = idx & 7;
        uint4 v = *reinterpret_cast<const uint4*>(g + (size_t)row * ldg + c * 8);
        *reinterpret_cast<uint4*>((char*)s + row * 144 + c * 16) = v;
    }
}

// ---------------- kernel 1: fp32 -> bf16 conversions (one fused launch) ----------------
__global__ void convert_all(const float4* __restrict__ W, const float4* __restrict__ hid,
                            const float4* __restrict__ Am, const float4* __restrict__ Bm) {
    const size_t NW = (size_t)VV * HH / 4;       // 16,384,000
    const size_t NH = (size_t)BB * SS * HH / 4;  //  2,097,152
    const size_t NA = (size_t)NSEGc * HH * 256 / 4;
    size_t gid = (size_t)blockIdx.x * 256 + threadIdx.x;
    float4 v;
    __nv_bfloat162* dst;
    if (gid < NW)                  { v = W[gid];              dst = (__nv_bfloat162*)g_Wbf + gid * 2; }
    else if (gid < NW + NH)        { size_t i = gid - NW;     v = hid[i]; dst = (__nv_bfloat162*)g_hid + i * 2; }
    else if (gid < NW + NH + NA)   { size_t i = gid - NW - NH; v = Am[i]; dst = (__nv_bfloat162*)g_Abf + i * 2; }
    else if (gid < NW + NH + 2*NA) { size_t i = gid - NW - NH - NA; v = Bm[i]; dst = (__nv_bfloat162*)g_Bbf + i * 2; }
    else return;
    __nv_bfloat162 p0, p1;
    p0.x = __float2bfloat16_rn(v.x); p0.y = __float2bfloat16_rn(v.y);
    p1.x = __float2bfloat16_rn(v.z); p1.y = __float2bfloat16_rn(v.w);
    dst[0] = p0; dst[1] = p1;
}

// ---------------- kernel 2: inter = gathered_x @ B_s^T ----------------
// grid = 16 segs * 2 n-tiles. M=128 (2 batches x 64 chunk rows), N=256, K=2048.
__global__ void __launch_bounds__(256, 2) gemm1_kernel(const int* __restrict__ starts) {
    __shared__ __nv_bfloat16 sA[128 * LDA];
    __shared__ __nv_bfloat16 sB[128 * LDA];
    int s = blockIdx.x >> 1, n0 = (blockIdx.x & 1) * 128;
    int tid = threadIdx.x, lane = tid & 31, warp = tid >> 5, mbase = warp * 16;
    int st0 = starts[0], st1 = starts[1];
    const __nv_bfloat16* Bbase = g_Bbf + ((size_t)s * 256 + n0) * HH;
    float acc[16][4];
#pragma unroll
    for (int j = 0; j < 16; j++) { acc[j][0] = acc[j][1] = acc[j][2] = acc[j][3] = 0.f; }
    for (int k0 = 0; k0 < HH; k0 += 64) {
        __syncthreads();
#pragma unroll
        for (int i = 0; i < 4; i++) {  // gather A rows: row -> (b, pos)
            int idx = tid + i * 256;
            int row = idx >> 3, c = idx & 7;
            int b = row >> 6;
            int pos = (b ? st1 : st0) + s * 64 + (row & 63);
            uint4 v = *reinterpret_cast<const uint4*>(
                g_hid + ((size_t)(b * SS + pos)) * HH + k0 + c * 8);
            *reinterpret_cast<uint4*>((char*)sA + row * 144 + c * 16) = v;
        }
        load_tile128(sB, Bbase + k0, HH, tid);
        __syncthreads();
        mma_ktile(acc, sA, sB, lane, mbase);
    }
    int g = lane >> 2, t4 = lane & 3;
    int r0 = mbase + g;
#pragma unroll
    for (int j = 0; j < 16; j++) {
        int col = n0 + 8 * j + 2 * t4;
        __nv_bfloat162 v01, v23;
        v01.x = __float2bfloat16_rn(acc[j][0]); v01.y = __float2bfloat16_rn(acc[j][1]);
        v23.x = __float2bfloat16_rn(acc[j][2]); v23.y = __float2bfloat16_rn(acc[j][3]);
        *reinterpret_cast<__nv_bfloat162*>(&g_inter[((size_t)s * 128 + r0) * 256 + col]) = v01;
        *reinterpret_cast<__nv_bfloat162*>(&g_inter[((size_t)s * 128 + r0 + 8) * 256 + col]) = v23;
    }
}

// ---------------- kernel 3: trans = inter @ A_s^T + bias ----------------
// grid = 16 segs * 16 n-tiles. M=128, N=2048, K=256.
__global__ void __launch_bounds__(256, 2) gemm2_kernel(const float* __restrict__ bias) {
    __shared__ __nv_bfloat16 sA[128 * LDA];
    __shared__ __nv_bfloat16 sB[128 * LDA];
    int s = blockIdx.x >> 4, n0 = (blockIdx.x & 15) * 128;
    int tid = threadIdx.x, lane = tid & 31, warp = tid >> 5, mbase = warp * 16;
    const __nv_bfloat16* Aba = g_inter + (size_t)s * 128 * 256;
    const __nv_bfloat16* Bba = g_Abf + ((size_t)s * HH + n0) * 256;
    float acc[16][4];
#pragma unroll
    for (int j = 0; j < 16; j++) { acc[j][0] = acc[j][1] = acc[j][2] = acc[j][3] = 0.f; }
    for (int k0 = 0; k0 < 256; k0 += 64) {
        __syncthreads();
        load_tile128(sA, Aba + k0, 256, tid);
        load_tile128(sB, Bba + k0, 256, tid);
        __syncthreads();
        mma_ktile(acc, sA, sB, lane, mbase);
    }
    int g = lane >> 2, t4 = lane & 3;
    int r0 = mbase + g, r1 = r0 + 8;
    int tok0r = (r0 >> 6) * TMm + s * 64 + (r0 & 63);
    int tok1r = (r1 >> 6) * TMm + s * 64 + (r1 & 63);
#pragma unroll
    for (int j = 0; j < 16; j++) {
        int col = n0 + 8 * j + 2 * t4;
        float b0 = bias[s * HH + col], b1 = bias[s * HH + col + 1];
        __nv_bfloat162 v01, v23;
        v01.x = __float2bfloat16_rn(acc[j][0] + b0); v01.y = __float2bfloat16_rn(acc[j][1] + b1);
        v23.x = __float2bfloat16_rn(acc[j][2] + b0); v23.y = __float2bfloat16_rn(acc[j][3] + b1);
        *reinterpret_cast<__nv_bfloat162*>(&g_trans[(size_t)tok0r * HH + col]) = v01;
        *reinterpret_cast<__nv_bfloat162*>(&g_trans[(size_t)tok1r * HH + col]) = v23;
    }
}

// ---------------- kernel 4: fused logits + online logsumexp ----------------
// grid = (48 M-tiles, 25 V-chunks). Per CTA: 128 tokens x 1280 vocab, K=2048.
// Writes per-token (running max, running sumexp) partials for its chunk.
__global__ void __launch_bounds__(256, 2) ce_kernel(const int* __restrict__ starts) {
    __shared__ __nv_bfloat16 sA[128 * LDA];
    __shared__ __nv_bfloat16 sB[128 * LDA];
    int mtile = blockIdx.x, chunk = blockIdx.y;
    int tid = threadIdx.x, lane = tid & 31, warp = tid >> 5, mbase = warp * 16;
    const __nv_bfloat16* Abase;
    if (mtile < 32) {
        int b = mtile >> 4, t0 = (mtile & 15) * 128;
        if (t0 + 127 < starts[b] - 1) return;   // tile entirely outside both masks
        Abase = g_hid + (size_t)mtile * 128 * HH;
    } else {
        Abase = g_trans + (size_t)(mtile - 32) * 128 * HH;
    }
    int tok0 = mtile * 128;
    float rm0 = -1e30f, rm1 = -1e30f, rs0 = 0.f, rs1 = 0.f;

    for (int it = 0; it < NT_PER_CTA; ++it) {
        const __nv_bfloat16* Bbase = g_Wbf + (size_t)(chunk * VCHUNK + it * 128) * HH;
        float acc[16][4];
#pragma unroll
        for (int j = 0; j < 16; j++) { acc[j][0] = acc[j][1] = acc[j][2] = acc[j][3] = 0.f; }
        for (int k0 = 0; k0 < HH; k0 += 64) {
            __syncthreads();
            load_tile128(sA, Abase + k0, HH, tid);
            load_tile128(sB, Bbase + k0, HH, tid);
            __syncthreads();
            mma_ktile(acc, sA, sB, lane, mbase);
        }
        // online softmax epilogue: rows (mbase+g) and (mbase+g+8)
        float t0m = -1e30f, t1m = -1e30f;
#pragma unroll
        for (int j = 0; j < 16; j++) {
            t0m = fmaxf(t0m, fmaxf(acc[j][0], acc[j][1]));
            t1m = fmaxf(t1m, fmaxf(acc[j][2], acc[j][3]));
        }
        t0m = fmaxf(t0m, __shfl_xor_sync(0xffffffffu, t0m, 1));
        t0m = fmaxf(t0m, __shfl_xor_sync(0xffffffffu, t0m, 2));
        t1m = fmaxf(t1m, __shfl_xor_sync(0xffffffffu, t1m, 1));
        t1m = fmaxf(t1m, __shfl_xor_sync(0xffffffffu, t1m, 2));
        float nm0 = fmaxf(rm0, t0m), nm1 = fmaxf(rm1, t1m);
        float ls0 = 0.f, ls1 = 0.f;
#pragma unroll
        for (int j = 0; j < 16; j++) {
            ls0 += __expf(acc[j][0] - nm0) + __expf(acc[j][1] - nm0);
            ls1 += __expf(acc[j][2] - nm1) + __expf(acc[j][3] - nm1);
        }
        ls0 += __shfl_xor_sync(0xffffffffu, ls0, 1);
        ls0 += __shfl_xor_sync(0xffffffffu, ls0, 2);
        ls1 += __shfl_xor_sync(0xffffffffu, ls1, 1);
        ls1 += __shfl_xor_sync(0xffffffffu, ls1, 2);
        rs0 = rs0 * __expf(rm0 - nm0) + ls0;
        rs1 = rs1 * __expf(rm1 - nm1) + ls1;
        rm0 = nm0; rm1 = nm1;
    }
    if ((lane & 3) == 0) {
        int r0 = tok0 + mbase + (lane >> 2);
        g_pm[chunk * NTOK + r0] = rm0;
        g_ps[chunk * NTOK + r0] = rs0;
        g_pm[chunk * NTOK + r0 + 8] = rm1;
        g_ps[chunk * NTOK + r0 + 8] = rs1;
    }
}

// ---------------- kernel 5: label logits (one warp per token) ----------------
__global__ void __launch_bounds__(256) labeldot_kernel(const int* __restrict__ ids,
                                                       const int* __restrict__ mlab) {
    int tok = blockIdx.x * 8 + (threadIdx.x >> 5);
    int lane = threadIdx.x & 31;
    const __nv_bfloat16* x;
    int label;
    if (tok < 4096) {
        int b = tok >> 11, t = tok & 2047;
        if (t >= 2047) { if (!lane) g_ld[tok] = 0.f; return; }
        x = g_hid + (size_t)tok * HH;
        label = ids[b * SS + t + 1];
    } else {
        x = g_trans + (size_t)(tok - 4096) * HH;
        label = mlab[tok - 4096];
    }
    const __nv_bfloat162* x2 = (const __nv_bfloat162*)x;
    const __nv_bfloat162* w2 = (const __nv_bfloat162*)(g_Wbf + (size_t)label * HH);
    float acc = 0.f;
    for (int i = lane; i < HH / 2; i += 32) {
        float2 a = __bfloat1622float2(x2[i]);
        float2 b = __bfloat1622float2(w2[i]);
        acc += a.x * b.x + a.y * b.y;
    }
#pragma unroll
    for (int o = 16; o; o >>= 1) acc += __shfl_xor_sync(0xffffffffu, acc, o);
    if (!lane) g_ld[tok] = acc;
}

// ---------------- kernel 6: combine partials, masked means, final losses ----------------
__global__ void __launch_bounds__(256) reduce_kernel(const int* __restrict__ starts,
                                                     const int* __restrict__ ends,
                                                     const int* __restrict__ attn,
                                                     const int* __restrict__ mmask,
                                                     float* __restrict__ out) {
    __shared__ int rl[2];
    __shared__ double red[6];
    int tid = threadIdx.x;
    if (tid < 2) rl[tid] = 0;
    if (tid < 6) red[tid] = 0.0;
    __syncthreads();
    int l0 = 0, l1 = 0;
    for (int i = tid; i < SS; i += 256) { l0 += attn[i]; l1 += attn[SS + i]; }
    atomicAdd(&rl[0], l0);
    atomicAdd(&rl[1], l1);
    __syncthreads();
    double s_st = 0, c_st = 0, s_fa = 0, c_fa = 0, s_m = 0, c_m = 0;
    for (int tok = tid; tok < NTOK; tok += 256) {
        float w_st = 0.f, w_fa = 0.f, w_m = 0.f;
        if (tok < 4096) {
            int b = tok >> 11, t = tok & 2047;
            if (t <= SS - 2) {
                if (t >= starts[b] - 1 && t <= ends[b] - 1) w_st = 1.f;
                if (t >= ends[b] && t < rl[b] - 1) w_fa = 1.f;
            }
        } else {
            if (mmask[tok - 4096]) w_m = 1.f;
        }
        if (w_st + w_fa + w_m > 0.f) {
            float m = -1e30f;
#pragma unroll 5
            for (int c = 0; c < NVC; c++) m = fmaxf(m, g_pm[c * NTOK + tok]);
            float s = 0.f;
#pragma unroll 5
            for (int c = 0; c < NVC; c++)
                s += g_ps[c * NTOK + tok] * expf(g_pm[c * NTOK + tok] - m);
            float nll = logf(s) + m - g_ld[tok];
            s_st += (double)(nll * w_st); c_st += w_st;
            s_fa += (double)(nll * w_fa); c_fa += w_fa;
            s_m  += (double)(nll * w_m);  c_m  += w_m;
        }
    }
    atomicAdd(&red[0], s_st); atomicAdd(&red[1], c_st);
    atomicAdd(&red[2], s_fa); atomicAdd(&red[3], c_fa);
    atomicAdd(&red[4], s_m);  atomicAdd(&red[5], c_m);
    __syncthreads();
    if (tid == 0) {
        double st = red[0] / fmax(red[1], 1.0);
        double fa = red[2] / fmax(red[3], 1.0);
        double ml = red[4] / fmax(red[5], 1.0);
        out[0] = (float)(0.5 * ml + 0.5 * st + 0.4 * fa);
        out[1] = (float)ml;
        out[2] = (float)st;
        out[3] = (float)fa;
    }
}

// ---------------- launch ----------------
extern "C" void kernel_launch(void* const* d_in, const int* in_sizes, int n_in,
                              void* d_out, int out_size) {
    const float* lhs    = (const float*)d_in[0];   // [2,2048,2048]
    const int*   ids    = (const int*)d_in[1];     // [2,2048]
    const int*   attn   = (const int*)d_in[2];     // [2,2048]
    const int*   starts = (const int*)d_in[3];     // [2]
    const int*   ends   = (const int*)d_in[4];     // [2]
    const int*   mlab   = (const int*)d_in[5];     // [2,1024]
    const int*   mmask  = (const int*)d_in[6];     // [2,1024]
    /* d_in[7] = math_lengths (int64) — unused by reference */
    const float* Am     = (const float*)d_in[8];   // [16,2048,256]
    const float* Bm     = (const float*)d_in[9];   // [16,256,2048]
    const float* bias   = (const float*)d_in[10];  // [16,2048]
    const float* W      = (const float*)d_in[11];  // [32000,2048]
    float* out = (float*)d_out;

    convert_all<<<88576, 256>>>((const float4*)W, (const float4*)lhs,
                                (const float4*)Am, (const float4*)Bm);
    gemm1_kernel<<<32, 256>>>(starts);
    gemm2_kernel<<<256, 256>>>(bias);
    ce_kernel<<<dim3(48, NVC), 256>>>(starts);
    labeldot_kernel<<<768, 256>>>(ids, mlab);
    reduce_kernel<<<1, 256>>>(starts, ends, attn, mmask, out);
    (void)in_sizes; (void)n_in; (void)out_size;
}

// round 3
// speedup vs baseline: 1.1120x; 1.1120x over previous
#include <cuda_runtime.h>
#include <cuda_bf16.h>
#include <cstdint>

// ---------------- problem constants ----------------
#define HH   2048
#define VV   32000
#define SS   2048
#define BB   2
#define TMm  1024
#define NSEGc 16
#define NTOK 6144          // 4096 main tokens + 2048 math tokens
#define NVC  25            // V chunks
#define VCHUNK 1280
#define CE_NT 10           // 128-wide n-tiles per chunk
#define LDA 72             // smem row stride in bf16 (144 B, conflict-free LDSM)

// ce smem layout: per buffer A(256x144B=36864) + B(128x144B=18432) = 55296; x2
#define CE_BUF_BYTES 55296u
#define CE_SMEM_BYTES (2 * 55296)

// ---------------- scratch (device globals; no allocs allowed) ----------------
__device__ __align__(16) __nv_bfloat16 g_Wbf[(size_t)VV * HH];          // 131 MB
__device__ __align__(16) __nv_bfloat16 g_hid[(size_t)BB * SS * HH];
__device__ __align__(16) __nv_bfloat16 g_Abf[(size_t)NSEGc * HH * 256];
__device__ __align__(16) __nv_bfloat16 g_Bbf[(size_t)NSEGc * 256 * HH];
__device__ __align__(16) __nv_bfloat16 g_inter[(size_t)NSEGc * 128 * 256];
__device__ __align__(16) __nv_bfloat16 g_trans[(size_t)BB * TMm * HH];
__device__ float g_pm[NVC * NTOK];
__device__ float g_ps[NVC * NTOK];
__device__ float g_ld[NTOK];

// ---------------- helpers ----------------
__device__ __forceinline__ uint32_t smem_u32(const void* p) {
    return (uint32_t)__cvta_generic_to_shared(p);
}
__device__ __forceinline__ void ldsm4(uint32_t* r, uint32_t a) {
    asm volatile("ldmatrix.sync.aligned.m8n8.x4.shared.b16 {%0,%1,%2,%3}, [%4];"
                 : "=r"(r[0]), "=r"(r[1]), "=r"(r[2]), "=r"(r[3]) : "r"(a));
}
__device__ __forceinline__ void mma_bf16(float* d, const uint32_t* a, const uint32_t* b) {
    asm volatile(
        "mma.sync.aligned.m16n8k16.row.col.f32.bf16.bf16.f32 "
        "{%0,%1,%2,%3},{%4,%5,%6,%7},{%8,%9},{%0,%1,%2,%3};"
        : "+f"(d[0]), "+f"(d[1]), "+f"(d[2]), "+f"(d[3])
        : "r"(a[0]), "r"(a[1]), "r"(a[2]), "r"(a[3]), "r"(b[0]), "r"(b[1]));
}
__device__ __forceinline__ void cp16(uint32_t s, const void* g) {
    asm volatile("cp.async.cg.shared.global [%0], [%1], 16;"
                 :: "r"(s), "l"(g) : "memory");
}
__device__ __forceinline__ void cp_commit() {
    asm volatile("cp.async.commit_group;" ::: "memory");
}
template <int N>
__device__ __forceinline__ void cp_wait() {
    asm volatile("cp.async.wait_group %0;" :: "n"(N) : "memory");
}

// HMMA 16x128 warp-tile k-slab (used by small adapter GEMMs)
__device__ __forceinline__ void mma_ktile(float acc[16][4], const __nv_bfloat16* sA,
                                          const __nv_bfloat16* sB, int lane, int mbase) {
#pragma unroll
    for (int kk = 0; kk < 64; kk += 16) {
        uint32_t a[4];
        ldsm4(a, smem_u32(sA + (mbase + (lane & 15)) * LDA + kk + ((lane >> 4) << 3)));
#pragma unroll
        for (int jp = 0; jp < 8; jp++) {
            uint32_t b[4];
            ldsm4(b, smem_u32(sB + ((jp * 2 + (lane >> 4)) * 8 + (lane & 7)) * LDA
                              + kk + (((lane >> 3) & 1) << 3)));
            mma_bf16(acc[2 * jp], a, b);
            mma_bf16(acc[2 * jp + 1], a, b + 2);
        }
    }
}
__device__ __forceinline__ void load_tile128(__nv_bfloat16* s, const __nv_bfloat16* g,
                                             int ldg, int tid) {
#pragma unroll
    for (int i = 0; i < 4; i++) {
        int idx = tid + i * 256;
        int row = idx >> 3, c = idx & 7;
        uint4 v = *reinterpret_cast<const uint4*>(g + (size_t)row * ldg + c * 8);
        *reinterpret_cast<uint4*>((char*)s + row * 144 + c * 16) = v;
    }
}

// ---------------- kernel 1: fp32 -> bf16 conversions ----------------
__global__ void convert_all(const float4* __restrict__ W, const float4* __restrict__ hid,
                            const float4* __restrict__ Am, const float4* __restrict__ Bm) {
    const size_t NW = (size_t)VV * HH / 4;
    const size_t NH = (size_t)BB * SS * HH / 4;
    const size_t NA = (size_t)NSEGc * HH * 256 / 4;
    size_t gid = (size_t)blockIdx.x * 256 + threadIdx.x;
    float4 v;
    __nv_bfloat162* dst;
    if (gid < NW)                  { v = W[gid];              dst = (__nv_bfloat162*)g_Wbf + gid * 2; }
    else if (gid < NW + NH)        { size_t i = gid - NW;     v = hid[i]; dst = (__nv_bfloat162*)g_hid + i * 2; }
    else if (gid < NW + NH + NA)   { size_t i = gid - NW - NH; v = Am[i]; dst = (__nv_bfloat162*)g_Abf + i * 2; }
    else if (gid < NW + NH + 2*NA) { size_t i = gid - NW - NH - NA; v = Bm[i]; dst = (__nv_bfloat162*)g_Bbf + i * 2; }
    else return;
    __nv_bfloat162 p0, p1;
    p0.x = __float2bfloat16_rn(v.x); p0.y = __float2bfloat16_rn(v.y);
    p1.x = __float2bfloat16_rn(v.z); p1.y = __float2bfloat16_rn(v.w);
    dst[0] = p0; dst[1] = p1;
}

// ---------------- kernel 2: inter = gathered_x @ B_s^T ----------------
__global__ void __launch_bounds__(256, 2) gemm1_kernel(const int* __restrict__ starts) {
    __shared__ __nv_bfloat16 sA[128 * LDA];
    __shared__ __nv_bfloat16 sB[128 * LDA];
    int s = blockIdx.x >> 1, n0 = (blockIdx.x & 1) * 128;
    int tid = threadIdx.x, lane = tid & 31, warp = tid >> 5, mbase = warp * 16;
    int st0 = starts[0], st1 = starts[1];
    const __nv_bfloat16* Bbase = g_Bbf + ((size_t)s * 256 + n0) * HH;
    float acc[16][4];
#pragma unroll
    for (int j = 0; j < 16; j++) { acc[j][0] = acc[j][1] = acc[j][2] = acc[j][3] = 0.f; }
    for (int k0 = 0; k0 < HH; k0 += 64) {
        __syncthreads();
#pragma unroll
        for (int i = 0; i < 4; i++) {
            int idx = tid + i * 256;
            int row = idx >> 3, c = idx & 7;
            int b = row >> 6;
            int pos = (b ? st1 : st0) + s * 64 + (row & 63);
            uint4 v = *reinterpret_cast<const uint4*>(
                g_hid + ((size_t)(b * SS + pos)) * HH + k0 + c * 8);
            *reinterpret_cast<uint4*>((char*)sA + row * 144 + c * 16) = v;
        }
        load_tile128(sB, Bbase + k0, HH, tid);
        __syncthreads();
        mma_ktile(acc, sA, sB, lane, mbase);
    }
    int g = lane >> 2, t4 = lane & 3;
    int r0 = mbase + g;
#pragma unroll
    for (int j = 0; j < 16; j++) {
        int col = n0 + 8 * j + 2 * t4;
        __nv_bfloat162 v01, v23;
        v01.x = __float2bfloat16_rn(acc[j][0]); v01.y = __float2bfloat16_rn(acc[j][1]);
        v23.x = __float2bfloat16_rn(acc[j][2]); v23.y = __float2bfloat16_rn(acc[j][3]);
        *reinterpret_cast<__nv_bfloat162*>(&g_inter[((size_t)s * 128 + r0) * 256 + col]) = v01;
        *reinterpret_cast<__nv_bfloat162*>(&g_inter[((size_t)s * 128 + r0 + 8) * 256 + col]) = v23;
    }
}

// ---------------- kernel 3: trans = inter @ A_s^T + bias ----------------
__global__ void __launch_bounds__(256, 2) gemm2_kernel(const float* __restrict__ bias) {
    __shared__ __nv_bfloat16 sA[128 * LDA];
    __shared__ __nv_bfloat16 sB[128 * LDA];
    int s = blockIdx.x >> 4, n0 = (blockIdx.x & 15) * 128;
    int tid = threadIdx.x, lane = tid & 31, warp = tid >> 5, mbase = warp * 16;
    const __nv_bfloat16* Aba = g_inter + (size_t)s * 128 * 256;
    const __nv_bfloat16* Bba = g_Abf + ((size_t)s * HH + n0) * 256;
    float acc[16][4];
#pragma unroll
    for (int j = 0; j < 16; j++) { acc[j][0] = acc[j][1] = acc[j][2] = acc[j][3] = 0.f; }
    for (int k0 = 0; k0 < 256; k0 += 64) {
        __syncthreads();
        load_tile128(sA, Aba + k0, 256, tid);
        load_tile128(sB, Bba + k0, 256, tid);
        __syncthreads();
        mma_ktile(acc, sA, sB, lane, mbase);
    }
    int g = lane >> 2, t4 = lane & 3;
    int r0 = mbase + g, r1 = r0 + 8;
    int tok0r = (r0 >> 6) * TMm + s * 64 + (r0 & 63);
    int tok1r = (r1 >> 6) * TMm + s * 64 + (r1 & 63);
#pragma unroll
    for (int j = 0; j < 16; j++) {
        int col = n0 + 8 * j + 2 * t4;
        float b0 = bias[s * HH + col], b1 = bias[s * HH + col + 1];
        __nv_bfloat162 v01, v23;
        v01.x = __float2bfloat16_rn(acc[j][0] + b0); v01.y = __float2bfloat16_rn(acc[j][1] + b1);
        v23.x = __float2bfloat16_rn(acc[j][2] + b0); v23.y = __float2bfloat16_rn(acc[j][3] + b1);
        *reinterpret_cast<__nv_bfloat162*>(&g_trans[(size_t)tok0r * HH + col]) = v01;
        *reinterpret_cast<__nv_bfloat162*>(&g_trans[(size_t)tok1r * HH + col]) = v23;
    }
}

// ---------------- kernel 4: fused logits + online logsumexp ----------------
// grid = (24 M-tiles of 256 tokens, 25 V-chunks). CTA tile 256x128, warp tile 32x128.
// cp.async double-buffered k-slabs (64 cols each).
__global__ void __launch_bounds__(256, 1) ce_kernel(const int* __restrict__ starts) {
    extern __shared__ char dsm[];
    const uint32_t sbase = smem_u32(dsm);
    int mtile = blockIdx.x, chunk = blockIdx.y;
    int tid = threadIdx.x, wid = tid >> 5, lane = tid & 31, mbase = wid * 32;

    const __nv_bfloat16* Abase;
    if (mtile < 16) {
        int b = mtile >> 3, t0 = (mtile & 7) * 256;
        if (t0 + 255 < starts[b] - 1) return;   // tile entirely outside both masks
        Abase = g_hid + (size_t)mtile * 256 * HH;
    } else {
        Abase = g_trans + (size_t)(mtile - 16) * 256 * HH;
    }
    int tok0 = mtile * 256;
    const __nv_bfloat16* Bchunk = g_Wbf + (size_t)(chunk * VCHUNK) * HH;

    auto issue_slab = [&](int buf, int nt, int sl) {
        uint32_t sa = sbase + (uint32_t)buf * CE_BUF_BYTES;
        uint32_t sb = sa + 36864u;
        int k0 = sl * 64;
        const __nv_bfloat16* Asrc = Abase + k0;
        const __nv_bfloat16* Bsrc = Bchunk + (size_t)(nt * 128) * HH + k0;
#pragma unroll
        for (int i = 0; i < 8; i++) {           // A: 256 rows x 128 B
            int idx = tid + i * 256;
            int r = idx >> 3, c = idx & 7;
            cp16(sa + (uint32_t)(r * 144 + c * 16), Asrc + (size_t)r * HH + c * 8);
        }
#pragma unroll
        for (int i = 0; i < 4; i++) {           // B: 128 vocab rows x 128 B
            int idx = tid + i * 256;
            int r = idx >> 3, c = idx & 7;
            cp16(sb + (uint32_t)(r * 144 + c * 16), Bsrc + (size_t)r * HH + c * 8);
        }
    };

    float rm[4] = {-1e30f, -1e30f, -1e30f, -1e30f};
    float rs[4] = {0.f, 0.f, 0.f, 0.f};

    issue_slab(0, 0, 0);
    cp_commit();
    int buf = 0;

    for (int nt = 0; nt < CE_NT; nt++) {
        float acc[2][16][4];
#pragma unroll
        for (int mi = 0; mi < 2; mi++)
#pragma unroll
            for (int j = 0; j < 16; j++) {
                acc[mi][j][0] = acc[mi][j][1] = acc[mi][j][2] = acc[mi][j][3] = 0.f;
            }
        for (int sl = 0; sl < 32; sl++) {
            int nnt = (sl == 31) ? nt + 1 : nt;
            int nsl = (sl == 31) ? 0 : sl + 1;
            if (nnt < CE_NT) {
                issue_slab(buf ^ 1, nnt, nsl);
                cp_commit();
                cp_wait<1>();
            } else {
                cp_wait<0>();
            }
            __syncthreads();
            uint32_t sa = sbase + (uint32_t)buf * CE_BUF_BYTES;
            uint32_t sb = sa + 36864u;
#pragma unroll
            for (int kk = 0; kk < 64; kk += 16) {
                uint32_t a0[4], a1[4];
                uint32_t arow = (uint32_t)(mbase + (lane & 15));
                uint32_t acol = (uint32_t)(kk + ((lane >> 4) << 3));
                ldsm4(a0, sa + arow * 144 + acol * 2);
                ldsm4(a1, sa + (arow + 16) * 144 + acol * 2);
#pragma unroll
                for (int jp = 0; jp < 8; jp++) {
                    uint32_t b[4];
                    uint32_t brow = (uint32_t)((jp * 2 + (lane >> 4)) * 8 + (lane & 7));
                    uint32_t bcol = (uint32_t)(kk + (((lane >> 3) & 1) << 3));
                    ldsm4(b, sb + brow * 144 + bcol * 2);
                    mma_bf16(acc[0][2 * jp], a0, b);
                    mma_bf16(acc[0][2 * jp + 1], a0, b + 2);
                    mma_bf16(acc[1][2 * jp], a1, b);
                    mma_bf16(acc[1][2 * jp + 1], a1, b + 2);
                }
            }
            __syncthreads();
            buf ^= 1;
        }
        // online logsumexp over this n-tile's 128 cols; 4 row-streams per thread
#pragma unroll
        for (int mi = 0; mi < 2; mi++) {
            float m0 = -1e30f, m1 = -1e30f;
#pragma unroll
            for (int j = 0; j < 16; j++) {
                m0 = fmaxf(m0, fmaxf(acc[mi][j][0], acc[mi][j][1]));
                m1 = fmaxf(m1, fmaxf(acc[mi][j][2], acc[mi][j][3]));
            }
            m0 = fmaxf(m0, __shfl_xor_sync(0xffffffffu, m0, 1));
            m0 = fmaxf(m0, __shfl_xor_sync(0xffffffffu, m0, 2));
            m1 = fmaxf(m1, __shfl_xor_sync(0xffffffffu, m1, 1));
            m1 = fmaxf(m1, __shfl_xor_sync(0xffffffffu, m1, 2));
            float nm0 = fmaxf(rm[mi * 2], m0), nm1 = fmaxf(rm[mi * 2 + 1], m1);
            float s0 = 0.f, s1 = 0.f;
#pragma unroll
            for (int j = 0; j < 16; j++) {
                s0 += __expf(acc[mi][j][0] - nm0) + __expf(acc[mi][j][1] - nm0);
                s1 += __expf(acc[mi][j][2] - nm1) + __expf(acc[mi][j][3] - nm1);
            }
            s0 += __shfl_xor_sync(0xffffffffu, s0, 1);
            s0 += __shfl_xor_sync(0xffffffffu, s0, 2);
            s1 += __shfl_xor_sync(0xffffffffu, s1, 1);
            s1 += __shfl_xor_sync(0xffffffffu, s1, 2);
            rs[mi * 2] = rs[mi * 2] * __expf(rm[mi * 2] - nm0) + s0;
            rs[mi * 2 + 1] = rs[mi * 2 + 1] * __expf(rm[mi * 2 + 1] - nm1) + s1;
            rm[mi * 2] = nm0;
            rm[mi * 2 + 1] = nm1;
        }
    }
    if ((lane & 3) == 0) {
        int g = lane >> 2;
        int rows[4] = {mbase + g, mbase + 8 + g, mbase + 16 + g, mbase + 24 + g};
#pragma unroll
        for (int k = 0; k < 4; k++) {
            g_pm[chunk * NTOK + tok0 + rows[k]] = rm[k];
            g_ps[chunk * NTOK + tok0 + rows[k]] = rs[k];
        }
    }
}

// ---------------- kernel 5: label logits ----------------
__global__ void __launch_bounds__(256) labeldot_kernel(const int* __restrict__ ids,
                                                       const int* __restrict__ mlab) {
    int tok = blockIdx.x * 8 + (threadIdx.x >> 5);
    int lane = threadIdx.x & 31;
    const __nv_bfloat16* x;
    int label;
    if (tok < 4096) {
        int b = tok >> 11, t = tok & 2047;
        if (t >= 2047) { if (!lane) g_ld[tok] = 0.f; return; }
        x = g_hid + (size_t)tok * HH;
        label = ids[b * SS + t + 1];
    } else {
        x = g_trans + (size_t)(tok - 4096) * HH;
        label = mlab[tok - 4096];
    }
    const __nv_bfloat162* x2 = (const __nv_bfloat162*)x;
    const __nv_bfloat162* w2 = (const __nv_bfloat162*)(g_Wbf + (size_t)label * HH);
    float acc = 0.f;
    for (int i = lane; i < HH / 2; i += 32) {
        float2 a = __bfloat1622float2(x2[i]);
        float2 b = __bfloat1622float2(w2[i]);
        acc += a.x * b.x + a.y * b.y;
    }
#pragma unroll
    for (int o = 16; o; o >>= 1) acc += __shfl_xor_sync(0xffffffffu, acc, o);
    if (!lane) g_ld[tok] = acc;
}

// ---------------- kernel 6: combine partials + masked means ----------------
__global__ void __launch_bounds__(256) reduce_kernel(const int* __restrict__ starts,
                                                     const int* __restrict__ ends,
                                                     const int* __restrict__ attn,
                                                     const int* __restrict__ mmask,
                                                     float* __restrict__ out) {
    __shared__ int rl[2];
    __shared__ double red[6];
    int tid = threadIdx.x;
    if (tid < 2) rl[tid] = 0;
    if (tid < 6) red[tid] = 0.0;
    __syncthreads();
    int l0 = 0, l1 = 0;
    for (int i = tid; i < SS; i += 256) { l0 += attn[i]; l1 += attn[SS + i]; }
    atomicAdd(&rl[0], l0);
    atomicAdd(&rl[1], l1);
    __syncthreads();
    double s_st = 0, c_st = 0, s_fa = 0, c_fa = 0, s_m = 0, c_m = 0;
    for (int tok = tid; tok < NTOK; tok += 256) {
        float w_st = 0.f, w_fa = 0.f, w_m = 0.f;
        if (tok < 4096) {
            int b = tok >> 11, t = tok & 2047;
            if (t <= SS - 2) {
                if (t >= starts[b] - 1 && t <= ends[b] - 1) w_st = 1.f;
                if (t >= ends[b] && t < rl[b] - 1) w_fa = 1.f;
            }
        } else {
            if (mmask[tok - 4096]) w_m = 1.f;
        }
        if (w_st + w_fa + w_m > 0.f) {
            float m = -1e30f;
#pragma unroll 5
            for (int c = 0; c < NVC; c++) m = fmaxf(m, g_pm[c * NTOK + tok]);
            float s = 0.f;
#pragma unroll 5
            for (int c = 0; c < NVC; c++)
                s += g_ps[c * NTOK + tok] * expf(g_pm[c * NTOK + tok] - m);
            float nll = logf(s) + m - g_ld[tok];
            s_st += (double)(nll * w_st); c_st += w_st;
            s_fa += (double)(nll * w_fa); c_fa += w_fa;
            s_m  += (double)(nll * w_m);  c_m  += w_m;
        }
    }
    atomicAdd(&red[0], s_st); atomicAdd(&red[1], c_st);
    atomicAdd(&red[2], s_fa); atomicAdd(&red[3], c_fa);
    atomicAdd(&red[4], s_m);  atomicAdd(&red[5], c_m);
    __syncthreads();
    if (tid == 0) {
        double st = red[0] / fmax(red[1], 1.0);
        double fa = red[2] / fmax(red[3], 1.0);
        double ml = red[4] / fmax(red[5], 1.0);
        out[0] = (float)(0.5 * ml + 0.5 * st + 0.4 * fa);
        out[1] = (float)ml;
        out[2] = (float)st;
        out[3] = (float)fa;
    }
}

// ---------------- launch ----------------
extern "C" void kernel_launch(void* const* d_in, const int* in_sizes, int n_in,
                              void* d_out, int out_size) {
    const float* lhs    = (const float*)d_in[0];
    const int*   ids    = (const int*)d_in[1];
    const int*   attn   = (const int*)d_in[2];
    const int*   starts = (const int*)d_in[3];
    const int*   ends   = (const int*)d_in[4];
    const int*   mlab   = (const int*)d_in[5];
    const int*   mmask  = (const int*)d_in[6];
    const float* Am     = (const float*)d_in[8];
    const float* Bm     = (const float*)d_in[9];
    const float* bias   = (const float*)d_in[10];
    const float* W      = (const float*)d_in[11];
    float* out = (float*)d_out;

    cudaFuncSetAttribute(ce_kernel, cudaFuncAttributeMaxDynamicSharedMemorySize,
                         CE_SMEM_BYTES);

    convert_all<<<88576, 256>>>((const float4*)W, (const float4*)lhs,
                                (const float4*)Am, (const float4*)Bm);
    gemm1_kernel<<<32, 256>>>(starts);
    gemm2_kernel<<<256, 256>>>(bias);
    ce_kernel<<<dim3(24, NVC), 256, CE_SMEM_BYTES>>>(starts);
    labeldot_kernel<<<768, 256>>>(ids, mlab);
    reduce_kernel<<<1, 256>>>(starts, ends, attn, mmask, out);
    (void)in_sizes; (void)n_in; (void)out_size;
}

// round 4
// speedup vs baseline: 1.2867x; 1.1571x over previous
#include <cuda_runtime.h>
#include <cuda_bf16.h>
#include <cstdint>

// ---------------- problem constants ----------------
#define HH   2048
#define VV   32000
#define SS   2048
#define BB   2
#define TMm  1024
#define NSEGc 16
#define NTOK 6144          // 4096 main tokens + 2048 math tokens
#define NVC  125           // V chunks (256 cols each)
#define CE_NT 2            // 128-wide n-tiles per chunk
#define LDA 72             // smem row stride in bf16 (144 B, conflict-free LDSM)

// ce smem: per stage A(256x144B=36864) + B(128x144B=18432) = 55296; 3 stages
#define CE_ABYTES 36864u
#define CE_BUF_BYTES 55296u
#define CE_SMEM_BYTES (3 * 55296)

// ---------------- scratch (device globals; no allocs allowed) ----------------
__device__ __align__(16) __nv_bfloat16 g_Wbf[(size_t)VV * HH];          // 131 MB
__device__ __align__(16) __nv_bfloat16 g_hid[(size_t)BB * SS * HH];
__device__ __align__(16) __nv_bfloat16 g_Abf[(size_t)NSEGc * HH * 256];
__device__ __align__(16) __nv_bfloat16 g_Bbf[(size_t)NSEGc * 256 * HH];
__device__ __align__(16) __nv_bfloat16 g_inter[(size_t)NSEGc * 128 * 256];
__device__ __align__(16) __nv_bfloat16 g_trans[(size_t)BB * TMm * HH];
__device__ float g_pm[NVC * NTOK];     // 3 MB
__device__ float g_ps[NVC * NTOK];     // 3 MB
__device__ float g_ld[NTOK];
__device__ float g_nll[NTOK];

// ---------------- helpers ----------------
__device__ __forceinline__ uint32_t smem_u32(const void* p) {
    return (uint32_t)__cvta_generic_to_shared(p);
}
__device__ __forceinline__ void ldsm4(uint32_t* r, uint32_t a) {
    asm volatile("ldmatrix.sync.aligned.m8n8.x4.shared.b16 {%0,%1,%2,%3}, [%4];"
                 : "=r"(r[0]), "=r"(r[1]), "=r"(r[2]), "=r"(r[3]) : "r"(a));
}
__device__ __forceinline__ void mma_bf16(float* d, const uint32_t* a, const uint32_t* b) {
    asm volatile(
        "mma.sync.aligned.m16n8k16.row.col.f32.bf16.bf16.f32 "
        "{%0,%1,%2,%3},{%4,%5,%6,%7},{%8,%9},{%0,%1,%2,%3};"
        : "+f"(d[0]), "+f"(d[1]), "+f"(d[2]), "+f"(d[3])
        : "r"(a[0]), "r"(a[1]), "r"(a[2]), "r"(a[3]), "r"(b[0]), "r"(b[1]));
}
__device__ __forceinline__ void cp16(uint32_t s, const void* g) {
    asm volatile("cp.async.cg.shared.global [%0], [%1], 16;"
                 :: "r"(s), "l"(g) : "memory");
}
__device__ __forceinline__ void cp_commit() {
    asm volatile("cp.async.commit_group;" ::: "memory");
}
template <int N>
__device__ __forceinline__ void cp_wait() {
    asm volatile("cp.async.wait_group %0;" :: "n"(N) : "memory");
}

// HMMA 16x128 warp-tile k-slab (small adapter GEMMs)
__device__ __forceinline__ void mma_ktile(float acc[16][4], const __nv_bfloat16* sA,
                                          const __nv_bfloat16* sB, int lane, int mbase) {
#pragma unroll
    for (int kk = 0; kk < 64; kk += 16) {
        uint32_t a[4];
        ldsm4(a, smem_u32(sA + (mbase + (lane & 15)) * LDA + kk + ((lane >> 4) << 3)));
#pragma unroll
        for (int jp = 0; jp < 8; jp++) {
            uint32_t b[4];
            ldsm4(b, smem_u32(sB + ((jp * 2 + (lane >> 4)) * 8 + (lane & 7)) * LDA
                              + kk + (((lane >> 3) & 1) << 3)));
            mma_bf16(acc[2 * jp], a, b);
            mma_bf16(acc[2 * jp + 1], a, b + 2);
        }
    }
}
__device__ __forceinline__ void load_tile128(__nv_bfloat16* s, const __nv_bfloat16* g,
                                             int ldg, int tid) {
#pragma unroll
    for (int i = 0; i < 4; i++) {
        int idx = tid + i * 256;
        int row = idx >> 3, c = idx & 7;
        uint4 v = *reinterpret_cast<const uint4*>(g + (size_t)row * ldg + c * 8);
        *reinterpret_cast<uint4*>((char*)s + row * 144 + c * 16) = v;
    }
}

// ---------------- kernel 1: fp32 -> bf16 conversions ----------------
__global__ void convert_all(const float4* __restrict__ W, const float4* __restrict__ hid,
                            const float4* __restrict__ Am, const float4* __restrict__ Bm) {
    const size_t NW = (size_t)VV * HH / 4;
    const size_t NH = (size_t)BB * SS * HH / 4;
    const size_t NA = (size_t)NSEGc * HH * 256 / 4;
    size_t gid = (size_t)blockIdx.x * 256 + threadIdx.x;
    float4 v;
    __nv_bfloat162* dst;
    if (gid < NW)                  { v = W[gid];              dst = (__nv_bfloat162*)g_Wbf + gid * 2; }
    else if (gid < NW + NH)        { size_t i = gid - NW;     v = hid[i]; dst = (__nv_bfloat162*)g_hid + i * 2; }
    else if (gid < NW + NH + NA)   { size_t i = gid - NW - NH; v = Am[i]; dst = (__nv_bfloat162*)g_Abf + i * 2; }
    else if (gid < NW + NH + 2*NA) { size_t i = gid - NW - NH - NA; v = Bm[i]; dst = (__nv_bfloat162*)g_Bbf + i * 2; }
    else return;
    __nv_bfloat162 p0, p1;
    p0.x = __float2bfloat16_rn(v.x); p0.y = __float2bfloat16_rn(v.y);
    p1.x = __float2bfloat16_rn(v.z); p1.y = __float2bfloat16_rn(v.w);
    dst[0] = p0; dst[1] = p1;
}

// ---------------- kernel 2: inter = gathered_x @ B_s^T ----------------
__global__ void __launch_bounds__(256, 2) gemm1_kernel(const int* __restrict__ starts) {
    __shared__ __nv_bfloat16 sA[128 * LDA];
    __shared__ __nv_bfloat16 sB[128 * LDA];
    int s = blockIdx.x >> 1, n0 = (blockIdx.x & 1) * 128;
    int tid = threadIdx.x, lane = tid & 31, warp = tid >> 5, mbase = warp * 16;
    int st0 = starts[0], st1 = starts[1];
    const __nv_bfloat16* Bbase = g_Bbf + ((size_t)s * 256 + n0) * HH;
    float acc[16][4];
#pragma unroll
    for (int j = 0; j < 16; j++) { acc[j][0] = acc[j][1] = acc[j][2] = acc[j][3] = 0.f; }
    for (int k0 = 0; k0 < HH; k0 += 64) {
        __syncthreads();
#pragma unroll
        for (int i = 0; i < 4; i++) {
            int idx = tid + i * 256;
            int row = idx >> 3, c = idx & 7;
            int b = row >> 6;
            int pos = (b ? st1 : st0) + s * 64 + (row & 63);
            uint4 v = *reinterpret_cast<const uint4*>(
                g_hid + ((size_t)(b * SS + pos)) * HH + k0 + c * 8);
            *reinterpret_cast<uint4*>((char*)sA + row * 144 + c * 16) = v;
        }
        load_tile128(sB, Bbase + k0, HH, tid);
        __syncthreads();
        mma_ktile(acc, sA, sB, lane, mbase);
    }
    int g = lane >> 2, t4 = lane & 3;
    int r0 = mbase + g;
#pragma unroll
    for (int j = 0; j < 16; j++) {
        int col = n0 + 8 * j + 2 * t4;
        __nv_bfloat162 v01, v23;
        v01.x = __float2bfloat16_rn(acc[j][0]); v01.y = __float2bfloat16_rn(acc[j][1]);
        v23.x = __float2bfloat16_rn(acc[j][2]); v23.y = __float2bfloat16_rn(acc[j][3]);
        *reinterpret_cast<__nv_bfloat162*>(&g_inter[((size_t)s * 128 + r0) * 256 + col]) = v01;
        *reinterpret_cast<__nv_bfloat162*>(&g_inter[((size_t)s * 128 + r0 + 8) * 256 + col]) = v23;
    }
}

// ---------------- kernel 3: trans = inter @ A_s^T + bias ----------------
__global__ void __launch_bounds__(256, 2) gemm2_kernel(const float* __restrict__ bias) {
    __shared__ __nv_bfloat16 sA[128 * LDA];
    __shared__ __nv_bfloat16 sB[128 * LDA];
    int s = blockIdx.x >> 4, n0 = (blockIdx.x & 15) * 128;
    int tid = threadIdx.x, lane = tid & 31, warp = tid >> 5, mbase = warp * 16;
    const __nv_bfloat16* Aba = g_inter + (size_t)s * 128 * 256;
    const __nv_bfloat16* Bba = g_Abf + ((size_t)s * HH + n0) * 256;
    float acc[16][4];
#pragma unroll
    for (int j = 0; j < 16; j++) { acc[j][0] = acc[j][1] = acc[j][2] = acc[j][3] = 0.f; }
    for (int k0 = 0; k0 < 256; k0 += 64) {
        __syncthreads();
        load_tile128(sA, Aba + k0, 256, tid);
        load_tile128(sB, Bba + k0, 256, tid);
        __syncthreads();
        mma_ktile(acc, sA, sB, lane, mbase);
    }
    int g = lane >> 2, t4 = lane & 3;
    int r0 = mbase + g, r1 = r0 + 8;
    int tok0r = (r0 >> 6) * TMm + s * 64 + (r0 & 63);
    int tok1r = (r1 >> 6) * TMm + s * 64 + (r1 & 63);
#pragma unroll
    for (int j = 0; j < 16; j++) {
        int col = n0 + 8 * j + 2 * t4;
        float b0 = bias[s * HH + col], b1 = bias[s * HH + col + 1];
        __nv_bfloat162 v01, v23;
        v01.x = __float2bfloat16_rn(acc[j][0] + b0); v01.y = __float2bfloat16_rn(acc[j][1] + b1);
        v23.x = __float2bfloat16_rn(acc[j][2] + b0); v23.y = __float2bfloat16_rn(acc[j][3] + b1);
        *reinterpret_cast<__nv_bfloat162*>(&g_trans[(size_t)tok0r * HH + col]) = v01;
        *reinterpret_cast<__nv_bfloat162*>(&g_trans[(size_t)tok1r * HH + col]) = v23;
    }
}

// ---------------- kernel 4: fused logits + online logsumexp ----------------
// grid = (24 M-tiles of 256 tokens, 125 V-chunks of 256 cols). 512 threads.
// CTA tile 256x128 per n-tile; warp tile 32x64 (16 warps: wm=wid>>1, wn=wid&1).
// 3-stage cp.async pipeline, one __syncthreads per slab.
__global__ void __launch_bounds__(512, 1) ce_kernel(const int* __restrict__ starts) {
    extern __shared__ char dsm[];
    const uint32_t sbase = smem_u32(dsm);
    int mtile = blockIdx.x, chunk = blockIdx.y;
    int tid = threadIdx.x, wid = tid >> 5, lane = tid & 31;
    int wm = wid >> 1, wn = wid & 1, mbase = wm * 32;

    const __nv_bfloat16* Abase;
    if (mtile < 16) {
        int b = mtile >> 3, t0 = (mtile & 7) * 256;
        if (t0 + 255 < starts[b] - 1) return;   // tile entirely outside both masks
        Abase = g_hid + (size_t)mtile * 256 * HH;
    } else {
        Abase = g_trans + (size_t)(mtile - 16) * 256 * HH;
    }
    int tok0 = mtile * 256;
    const __nv_bfloat16* Bchunk = g_Wbf + (size_t)(chunk * CE_NT * 128) * HH;
    const int TOT = CE_NT * 32;

    auto issue = [&](int s) {
        uint32_t sa = sbase + (uint32_t)(s % 3) * CE_BUF_BYTES;
        uint32_t sb = sa + CE_ABYTES;
        int k0 = (s & 31) * 64;
        const __nv_bfloat16* Asrc = Abase + k0;
        const __nv_bfloat16* Bsrc = Bchunk + (size_t)((s >> 5) * 128) * HH + k0;
#pragma unroll
        for (int i = 0; i < 4; i++) {          // A: 256 rows x 128 B
            int idx = tid + i * 512;
            int r = idx >> 3, c = idx & 7;
            cp16(sa + (uint32_t)(r * 144 + c * 16), Asrc + (size_t)r * HH + c * 8);
        }
#pragma unroll
        for (int i = 0; i < 2; i++) {          // B: 128 vocab rows x 128 B
            int idx = tid + i * 512;
            int r = idx >> 3, c = idx & 7;
            cp16(sb + (uint32_t)(r * 144 + c * 16), Bsrc + (size_t)r * HH + c * 8);
        }
        cp_commit();
    };

    float rm[4] = {-1e30f, -1e30f, -1e30f, -1e30f};
    float rs[4] = {0.f, 0.f, 0.f, 0.f};

    issue(0);
    issue(1);

    for (int nt = 0; nt < CE_NT; nt++) {
        float acc[2][8][4];
#pragma unroll
        for (int mi = 0; mi < 2; mi++)
#pragma unroll
            for (int j = 0; j < 8; j++) {
                acc[mi][j][0] = acc[mi][j][1] = acc[mi][j][2] = acc[mi][j][3] = 0.f;
            }
        for (int sl = 0; sl < 32; sl++) {
            int s = nt * 32 + sl;
            if (s < TOT - 1) cp_wait<1>(); else cp_wait<0>();
            __syncthreads();               // slab s ready; compute(s-1) done everywhere
            if (s + 2 < TOT) issue(s + 2); // overwrites buffer computed at iter s-1
            uint32_t sa = sbase + (uint32_t)(s % 3) * CE_BUF_BYTES;
            uint32_t sb = sa + CE_ABYTES;
#pragma unroll
            for (int kk = 0; kk < 64; kk += 16) {
                uint32_t a0[4], a1[4];
                uint32_t arow = (uint32_t)(mbase + (lane & 15));
                uint32_t acol = (uint32_t)(kk + ((lane >> 4) << 3));
                ldsm4(a0, sa + arow * 144 + acol * 2);
                ldsm4(a1, sa + (arow + 16) * 144 + acol * 2);
#pragma unroll
                for (int jp = 0; jp < 4; jp++) {
                    uint32_t b[4];
                    uint32_t brow = (uint32_t)(((wn * 4 + jp) * 2 + (lane >> 4)) * 8 + (lane & 7));
                    uint32_t bcol = (uint32_t)(kk + (((lane >> 3) & 1) << 3));
                    ldsm4(b, sb + brow * 144 + bcol * 2);
                    mma_bf16(acc[0][2 * jp], a0, b);
                    mma_bf16(acc[0][2 * jp + 1], a0, b + 2);
                    mma_bf16(acc[1][2 * jp], a1, b);
                    mma_bf16(acc[1][2 * jp + 1], a1, b + 2);
                }
            }
        }
        // online logsumexp over this n-tile's 64 cols; 4 row-streams per thread
#pragma unroll
        for (int mi = 0; mi < 2; mi++) {
            float m0 = -1e30f, m1 = -1e30f;
#pragma unroll
            for (int j = 0; j < 8; j++) {
                m0 = fmaxf(m0, fmaxf(acc[mi][j][0], acc[mi][j][1]));
                m1 = fmaxf(m1, fmaxf(acc[mi][j][2], acc[mi][j][3]));
            }
            m0 = fmaxf(m0, __shfl_xor_sync(0xffffffffu, m0, 1));
            m0 = fmaxf(m0, __shfl_xor_sync(0xffffffffu, m0, 2));
            m1 = fmaxf(m1, __shfl_xor_sync(0xffffffffu, m1, 1));
            m1 = fmaxf(m1, __shfl_xor_sync(0xffffffffu, m1, 2));
            float nm0 = fmaxf(rm[mi * 2], m0), nm1 = fmaxf(rm[mi * 2 + 1], m1);
            float s0 = 0.f, s1 = 0.f;
#pragma unroll
            for (int j = 0; j < 8; j++) {
                s0 += __expf(acc[mi][j][0] - nm0) + __expf(acc[mi][j][1] - nm0);
                s1 += __expf(acc[mi][j][2] - nm1) + __expf(acc[mi][j][3] - nm1);
            }
            s0 += __shfl_xor_sync(0xffffffffu, s0, 1);
            s0 += __shfl_xor_sync(0xffffffffu, s0, 2);
            s1 += __shfl_xor_sync(0xffffffffu, s1, 1);
            s1 += __shfl_xor_sync(0xffffffffu, s1, 2);
            rs[mi * 2] = rs[mi * 2] * __expf(rm[mi * 2] - nm0) + s0;
            rs[mi * 2 + 1] = rs[mi * 2 + 1] * __expf(rm[mi * 2 + 1] - nm1) + s1;
            rm[mi * 2] = nm0;
            rm[mi * 2 + 1] = nm1;
        }
    }
    // combine the two col-half warps (wn=0/1) that own the same rows
    __syncthreads();
    float2* ex = (float2*)dsm;   // 256 entries, reuses stage buffers (compute done)
    int g = lane >> 2;
    if (wn == 1 && (lane & 3) == 0) {
#pragma unroll
        for (int k = 0; k < 4; k++) {
            float2 v; v.x = rm[k]; v.y = rs[k];
            ex[mbase + g + k * 8] = v;
        }
    }
    __syncthreads();
    if (wn == 0 && (lane & 3) == 0) {
#pragma unroll
        for (int k = 0; k < 4; k++) {
            int row = mbase + g + k * 8;
            float2 o = ex[row];
            float m = fmaxf(rm[k], o.x);
            float s = rs[k] * __expf(rm[k] - m) + o.y * __expf(o.x - m);
            g_pm[chunk * NTOK + tok0 + row] = m;
            g_ps[chunk * NTOK + tok0 + row] = s;
        }
    }
}

// ---------------- kernel 5: label logits ----------------
__global__ void __launch_bounds__(256) labeldot_kernel(const int* __restrict__ ids,
                                                       const int* __restrict__ mlab) {
    int tok = blockIdx.x * 8 + (threadIdx.x >> 5);
    int lane = threadIdx.x & 31;
    const __nv_bfloat16* x;
    int label;
    if (tok < 4096) {
        int b = tok >> 11, t = tok & 2047;
        if (t >= 2047) { if (!lane) g_ld[tok] = 0.f; return; }
        x = g_hid + (size_t)tok * HH;
        label = ids[b * SS + t + 1];
    } else {
        x = g_trans + (size_t)(tok - 4096) * HH;
        label = mlab[tok - 4096];
    }
    const __nv_bfloat162* x2 = (const __nv_bfloat162*)x;
    const __nv_bfloat162* w2 = (const __nv_bfloat162*)(g_Wbf + (size_t)label * HH);
    float acc = 0.f;
    for (int i = lane; i < HH / 2; i += 32) {
        float2 a = __bfloat1622float2(x2[i]);
        float2 b = __bfloat1622float2(w2[i]);
        acc += a.x * b.x + a.y * b.y;
    }
#pragma unroll
    for (int o = 16; o; o >>= 1) acc += __shfl_xor_sync(0xffffffffu, acc, o);
    if (!lane) g_ld[tok] = acc;
}

// ---------------- kernel 5b: combine 125 chunk partials -> per-token nll ----------------
__global__ void __launch_bounds__(256) nll_kernel() {
    int tok = blockIdx.x * 256 + threadIdx.x;
    if (tok >= NTOK) return;
    float m = -1e30f;
    for (int c = 0; c < NVC; c++) m = fmaxf(m, g_pm[c * NTOK + tok]);
    float s = 0.f;
    for (int c = 0; c < NVC; c++)
        s += g_ps[c * NTOK + tok] * __expf(g_pm[c * NTOK + tok] - m);
    g_nll[tok] = __logf(s) + m - g_ld[tok];
}

// ---------------- kernel 6: masked means ----------------
__global__ void __launch_bounds__(256) reduce_kernel(const int* __restrict__ starts,
                                                     const int* __restrict__ ends,
                                                     const int* __restrict__ attn,
                                                     const int* __restrict__ mmask,
                                                     float* __restrict__ out) {
    __shared__ int rl[2];
    __shared__ double red[6];
    int tid = threadIdx.x;
    if (tid < 2) rl[tid] = 0;
    if (tid < 6) red[tid] = 0.0;
    __syncthreads();
    int l0 = 0, l1 = 0;
    for (int i = tid; i < SS; i += 256) { l0 += attn[i]; l1 += attn[SS + i]; }
    atomicAdd(&rl[0], l0);
    atomicAdd(&rl[1], l1);
    __syncthreads();
    double s_st = 0, c_st = 0, s_fa = 0, c_fa = 0, s_m = 0, c_m = 0;
    for (int tok = tid; tok < NTOK; tok += 256) {
        float w_st = 0.f, w_fa = 0.f, w_m = 0.f;
        if (tok < 4096) {
            int b = tok >> 11, t = tok & 2047;
            if (t <= SS - 2) {
                if (t >= starts[b] - 1 && t <= ends[b] - 1) w_st = 1.f;
                if (t >= ends[b] && t < rl[b] - 1) w_fa = 1.f;
            }
        } else {
            if (mmask[tok - 4096]) w_m = 1.f;
        }
        if (w_st + w_fa + w_m > 0.f) {
            float nll = g_nll[tok];
            s_st += (double)(nll * w_st); c_st += w_st;
            s_fa += (double)(nll * w_fa); c_fa += w_fa;
            s_m  += (double)(nll * w_m);  c_m  += w_m;
        }
    }
    atomicAdd(&red[0], s_st); atomicAdd(&red[1], c_st);
    atomicAdd(&red[2], s_fa); atomicAdd(&red[3], c_fa);
    atomicAdd(&red[4], s_m);  atomicAdd(&red[5], c_m);
    __syncthreads();
    if (tid == 0) {
        double st = red[0] / fmax(red[1], 1.0);
        double fa = red[2] / fmax(red[3], 1.0);
        double ml = red[4] / fmax(red[5], 1.0);
        out[0] = (float)(0.5 * ml + 0.5 * st + 0.4 * fa);
        out[1] = (float)ml;
        out[2] = (float)st;
        out[3] = (float)fa;
    }
}

// ---------------- launch ----------------
extern "C" void kernel_launch(void* const* d_in, const int* in_sizes, int n_in,
                              void* d_out, int out_size) {
    const float* lhs    = (const float*)d_in[0];
    const int*   ids    = (const int*)d_in[1];
    const int*   attn   = (const int*)d_in[2];
    const int*   starts = (const int*)d_in[3];
    const int*   ends   = (const int*)d_in[4];
    const int*   mlab   = (const int*)d_in[5];
    const int*   mmask  = (const int*)d_in[6];
    const float* Am     = (const float*)d_in[8];
    const float* Bm     = (const float*)d_in[9];
    const float* bias   = (const float*)d_in[10];
    const float* W      = (const float*)d_in[11];
    float* out = (float*)d_out;

    cudaFuncSetAttribute(ce_kernel, cudaFuncAttributeMaxDynamicSharedMemorySize,
                         CE_SMEM_BYTES);

    convert_all<<<88576, 256>>>((const float4*)W, (const float4*)lhs,
                                (const float4*)Am, (const float4*)Bm);
    gemm1_kernel<<<32, 256>>>(starts);
    gemm2_kernel<<<256, 256>>>(bias);
    ce_kernel<<<dim3(24, NVC), 512, CE_SMEM_BYTES>>>(starts);
    labeldot_kernel<<<768, 256>>>(ids, mlab);
    nll_kernel<<<24, 256>>>();
    reduce_kernel<<<1, 256>>>(starts, ends, attn, mmask, out);
    (void)in_sizes; (void)n_in; (void)out_size;
}

// round 7
// speedup vs baseline: 1.4092x; 1.0952x over previous
#include <cuda_runtime.h>
#include <cuda_bf16.h>
#include <cstdint>

// ---------------- problem constants ----------------
#define HH   2048
#define VV   32000
#define SS   2048
#define BB   2
#define TMm  1024
#define NSEGc 16
#define NTOK 6144          // 4096 main tokens + 2048 math tokens
#define NVC  125           // V chunks (256 cols each)
#define CE_NT 2            // 128-wide n-tiles per chunk
#define LDA 72             // smem row stride in bf16 (144 B, conflict-free LDSM)

// ce smem: per stage A(128x144B) + B(128x144B) = 36864; 3 stages = 110592
#define CE_STAGE_BYTES 36864u
#define CE_SMEM_BYTES (3 * 36864)

// ---------------- scratch (device globals; no allocs allowed) ----------------
__device__ __align__(16) __nv_bfloat16 g_Wbf[(size_t)VV * HH];          // 131 MB
__device__ __align__(16) __nv_bfloat16 g_hid[(size_t)BB * SS * HH];
__device__ __align__(16) __nv_bfloat16 g_Abf[(size_t)NSEGc * HH * 256];
__device__ __align__(16) __nv_bfloat16 g_Bbf[(size_t)NSEGc * 256 * HH];
__device__ __align__(16) __nv_bfloat16 g_inter[(size_t)NSEGc * 128 * 256];
__device__ __align__(16) __nv_bfloat16 g_trans[(size_t)BB * TMm * HH];
__device__ float g_pm[NVC * NTOK];     // 3 MB
__device__ float g_ps[NVC * NTOK];     // 3 MB
__device__ float g_ld[NTOK];
__device__ float g_nll[NTOK];

// ---------------- helpers ----------------
__device__ __forceinline__ uint32_t smem_u32(const void* p) {
    return (uint32_t)__cvta_generic_to_shared(p);
}
__device__ __forceinline__ void ldsm4(uint32_t* r, uint32_t a) {
    asm volatile("ldmatrix.sync.aligned.m8n8.x4.shared.b16 {%0,%1,%2,%3}, [%4];"
                 : "=r"(r[0]), "=r"(r[1]), "=r"(r[2]), "=r"(r[3]) : "r"(a));
}
__device__ __forceinline__ void mma_bf16(float* d, const uint32_t* a, const uint32_t* b) {
    asm volatile(
        "mma.sync.aligned.m16n8k16.row.col.f32.bf16.bf16.f32 "
        "{%0,%1,%2,%3},{%4,%5,%6,%7},{%8,%9},{%0,%1,%2,%3};"
        : "+f"(d[0]), "+f"(d[1]), "+f"(d[2]), "+f"(d[3])
        : "r"(a[0]), "r"(a[1]), "r"(a[2]), "r"(a[3]), "r"(b[0]), "r"(b[1]));
}
__device__ __forceinline__ void cp16(uint32_t s, const void* g) {
    asm volatile("cp.async.cg.shared.global [%0], [%1], 16;"
                 :: "r"(s), "l"(g) : "memory");
}
__device__ __forceinline__ void cp_commit() {
    asm volatile("cp.async.commit_group;" ::: "memory");
}
template <int N>
__device__ __forceinline__ void cp_wait() {
    asm volatile("cp.async.wait_group %0;" :: "n"(N) : "memory");
}

// HMMA 16x128 warp-tile k-slab (small adapter GEMMs)
__device__ __forceinline__ void mma_ktile(float acc[16][4], const __nv_bfloat16* sA,
                                          const __nv_bfloat16* sB, int lane, int mbase) {
#pragma unroll
    for (int kk = 0; kk < 64; kk += 16) {
        uint32_t a[4];
        ldsm4(a, smem_u32(sA + (mbase + (lane & 15)) * LDA + kk + ((lane >> 4) << 3)));
#pragma unroll
        for (int jp = 0; jp < 8; jp++) {
            uint32_t b[4];
            ldsm4(b, smem_u32(sB + ((jp * 2 + (lane >> 4)) * 8 + (lane & 7)) * LDA
                              + kk + (((lane >> 3) & 1) << 3)));
            mma_bf16(acc[2 * jp], a, b);
            mma_bf16(acc[2 * jp + 1], a, b + 2);
        }
    }
}
__device__ __forceinline__ void load_tile128(__nv_bfloat16* s, const __nv_bfloat16* g,
                                             int ldg, int tid) {
#pragma unroll
    for (int i = 0; i < 4; i++) {
        int idx = tid + i * 256;
        int row = idx >> 3, c = idx & 7;
        uint4 v = *reinterpret_cast<const uint4*>(g + (size_t)row * ldg + c * 8);
        *reinterpret_cast<uint4*>((char*)s + row * 144 + c * 16) = v;
    }
}

// ---------------- kernel 1: fp32 -> bf16 conversions ----------------
__global__ void convert_all(const float4* __restrict__ W, const float4* __restrict__ hid,
                            const float4* __restrict__ Am, const float4* __restrict__ Bm) {
    const size_t NW = (size_t)VV * HH / 4;
    const size_t NH = (size_t)BB * SS * HH / 4;
    const size_t NA = (size_t)NSEGc * HH * 256 / 4;
    size_t gid = (size_t)blockIdx.x * 256 + threadIdx.x;
    float4 v;
    __nv_bfloat162* dst;
    if (gid < NW)                  { v = W[gid];              dst = (__nv_bfloat162*)g_Wbf + gid * 2; }
    else if (gid < NW + NH)        { size_t i = gid - NW;     v = hid[i]; dst = (__nv_bfloat162*)g_hid + i * 2; }
    else if (gid < NW + NH + NA)   { size_t i = gid - NW - NH; v = Am[i]; dst = (__nv_bfloat162*)g_Abf + i * 2; }
    else if (gid < NW + NH + 2*NA) { size_t i = gid - NW - NH - NA; v = Bm[i]; dst = (__nv_bfloat162*)g_Bbf + i * 2; }
    else return;
    __nv_bfloat162 p0, p1;
    p0.x = __float2bfloat16_rn(v.x); p0.y = __float2bfloat16_rn(v.y);
    p1.x = __float2bfloat16_rn(v.z); p1.y = __float2bfloat16_rn(v.w);
    dst[0] = p0; dst[1] = p1;
}

// ---------------- kernel 2: inter = gathered_x @ B_s^T ----------------
__global__ void __launch_bounds__(256, 2) gemm1_kernel(const int* __restrict__ starts) {
    __shared__ __nv_bfloat16 sA[128 * LDA];
    __shared__ __nv_bfloat16 sB[128 * LDA];
    int s = blockIdx.x >> 1, n0 = (blockIdx.x & 1) * 128;
    int tid = threadIdx.x, lane = tid & 31, warp = tid >> 5, mbase = warp * 16;
    int st0 = starts[0], st1 = starts[1];
    const __nv_bfloat16* Bbase = g_Bbf + ((size_t)s * 256 + n0) * HH;
    float acc[16][4];
#pragma unroll
    for (int j = 0; j < 16; j++) { acc[j][0] = acc[j][1] = acc[j][2] = acc[j][3] = 0.f; }
    for (int k0 = 0; k0 < HH; k0 += 64) {
        __syncthreads();
#pragma unroll
        for (int i = 0; i < 4; i++) {
            int idx = tid + i * 256;
            int row = idx >> 3, c = idx & 7;
            int b = row >> 6;
            int pos = (b ? st1 : st0) + s * 64 + (row & 63);
            uint4 v = *reinterpret_cast<const uint4*>(
                g_hid + ((size_t)(b * SS + pos)) * HH + k0 + c * 8);
            *reinterpret_cast<uint4*>((char*)sA + row * 144 + c * 16) = v;
        }
        load_tile128(sB, Bbase + k0, HH, tid);
        __syncthreads();
        mma_ktile(acc, sA, sB, lane, mbase);
    }
    int g = lane >> 2, t4 = lane & 3;
    int r0 = mbase + g;
#pragma unroll
    for (int j = 0; j < 16; j++) {
        int col = n0 + 8 * j + 2 * t4;
        __nv_bfloat162 v01, v23;
        v01.x = __float2bfloat16_rn(acc[j][0]); v01.y = __float2bfloat16_rn(acc[j][1]);
        v23.x = __float2bfloat16_rn(acc[j][2]); v23.y = __float2bfloat16_rn(acc[j][3]);
        *reinterpret_cast<__nv_bfloat162*>(&g_inter[((size_t)s * 128 + r0) * 256 + col]) = v01;
        *reinterpret_cast<__nv_bfloat162*>(&g_inter[((size_t)s * 128 + r0 + 8) * 256 + col]) = v23;
    }
}

// ---------------- kernel 3: trans = inter @ A_s^T + bias ----------------
__global__ void __launch_bounds__(256, 2) gemm2_kernel(const float* __restrict__ bias) {
    __shared__ __nv_bfloat16 sA[128 * LDA];
    __shared__ __nv_bfloat16 sB[128 * LDA];
    int s = blockIdx.x >> 4, n0 = (blockIdx.x & 15) * 128;
    int tid = threadIdx.x, lane = tid & 31, warp = tid >> 5, mbase = warp * 16;
    const __nv_bfloat16* Aba = g_inter + (size_t)s * 128 * 256;
    const __nv_bfloat16* Bba = g_Abf + ((size_t)s * HH + n0) * 256;
    float acc[16][4];
#pragma unroll
    for (int j = 0; j < 16; j++) { acc[j][0] = acc[j][1] = acc[j][2] = acc[j][3] = 0.f; }
    for (int k0 = 0; k0 < 256; k0 += 64) {
        __syncthreads();
        load_tile128(sA, Aba + k0, 256, tid);
        load_tile128(sB, Bba + k0, 256, tid);
        __syncthreads();
        mma_ktile(acc, sA, sB, lane, mbase);
    }
    int g = lane >> 2, t4 = lane & 3;
    int r0 = mbase + g, r1 = r0 + 8;
    int tok0r = (r0 >> 6) * TMm + s * 64 + (r0 & 63);
    int tok1r = (r1 >> 6) * TMm + s * 64 + (r1 & 63);
#pragma unroll
    for (int j = 0; j < 16; j++) {
        int col = n0 + 8 * j + 2 * t4;
        float b0 = bias[s * HH + col], b1 = bias[s * HH + col + 1];
        __nv_bfloat162 v01, v23;
        v01.x = __float2bfloat16_rn(acc[j][0] + b0); v01.y = __float2bfloat16_rn(acc[j][1] + b1);
        v23.x = __float2bfloat16_rn(acc[j][2] + b0); v23.y = __float2bfloat16_rn(acc[j][3] + b1);
        *reinterpret_cast<__nv_bfloat162*>(&g_trans[(size_t)tok0r * HH + col]) = v01;
        *reinterpret_cast<__nv_bfloat162*>(&g_trans[(size_t)tok1r * HH + col]) = v23;
    }
}

// ---------------- kernel 4: fused logits + online logsumexp ----------------
// grid = (48 M-tiles of 128 tokens, 125 V-chunks of 256 cols). 256 threads,
// 2 CTAs/SM. CTA tile 128x128 per n-tile; warp tile 32x64 (wm=wid>>1, wn=wid&1).
// 3-stage cp.async pipeline, one __syncthreads per slab.
__global__ void __launch_bounds__(256, 2) ce_kernel(const int* __restrict__ starts) {
    extern __shared__ char dsm[];
    const uint32_t sbase = smem_u32(dsm);
    int mtile = blockIdx.x, chunk = blockIdx.y;
    int tid = threadIdx.x, wid = tid >> 5, lane = tid & 31;
    int wm = wid >> 1, wn = wid & 1, mbase = wm * 32;

    const __nv_bfloat16* Abase;
    if (mtile < 32) {
        int b = mtile >> 4, t0 = (mtile & 15) * 128;
        if (t0 + 127 < starts[b] - 1) return;   // tile entirely outside both masks
        Abase = g_hid + (size_t)mtile * 128 * HH;
    } else {
        Abase = g_trans + (size_t)(mtile - 32) * 128 * HH;
    }
    int tok0 = mtile * 128;
    const __nv_bfloat16* Bchunk = g_Wbf + (size_t)(chunk * CE_NT * 128) * HH;
    const int TOT = CE_NT * 32;

    auto issue = [&](int s) {
        uint32_t sa = sbase + (uint32_t)(s % 3) * CE_STAGE_BYTES;
        uint32_t sb = sa + 18432u;
        int k0 = (s & 31) * 64;
        const __nv_bfloat16* Asrc = Abase + k0;
        const __nv_bfloat16* Bsrc = Bchunk + (size_t)((s >> 5) * 128) * HH + k0;
#pragma unroll
        for (int i = 0; i < 4; i++) {          // A: 128 rows x 128 B
            int idx = tid + i * 256;
            int r = idx >> 3, c = idx & 7;
            cp16(sa + (uint32_t)(r * 144 + c * 16), Asrc + (size_t)r * HH + c * 8);
        }
#pragma unroll
        for (int i = 0; i < 4; i++) {          // B: 128 vocab rows x 128 B
            int idx = tid + i * 256;
            int r = idx >> 3, c = idx & 7;
            cp16(sb + (uint32_t)(r * 144 + c * 16), Bsrc + (size_t)r * HH + c * 8);
        }
        cp_commit();
    };

    float rm[4] = {-1e30f, -1e30f, -1e30f, -1e30f};
    float rs[4] = {0.f, 0.f, 0.f, 0.f};

    issue(0);
    issue(1);

    for (int nt = 0; nt < CE_NT; nt++) {
        float acc[2][8][4];
#pragma unroll
        for (int mi = 0; mi < 2; mi++)
#pragma unroll
            for (int j = 0; j < 8; j++) {
                acc[mi][j][0] = acc[mi][j][1] = acc[mi][j][2] = acc[mi][j][3] = 0.f;
            }
        for (int sl = 0; sl < 32; sl++) {
            int s = nt * 32 + sl;
            if (s < TOT - 1) cp_wait<1>(); else cp_wait<0>();
            __syncthreads();               // slab s ready; compute(s-1) done everywhere
            if (s + 2 < TOT) issue(s + 2); // overwrites buffer computed at iter s-1
            uint32_t sa = sbase + (uint32_t)(s % 3) * CE_STAGE_BYTES;
            uint32_t sb = sa + 18432u;
#pragma unroll
            for (int kk = 0; kk < 64; kk += 16) {
                uint32_t a0[4], a1[4];
                uint32_t arow = (uint32_t)(mbase + (lane & 15));
                uint32_t acol = (uint32_t)(kk + ((lane >> 4) << 3));
                ldsm4(a0, sa + arow * 144 + acol * 2);
                ldsm4(a1, sa + (arow + 16) * 144 + acol * 2);
#pragma unroll
                for (int jp = 0; jp < 4; jp++) {
                    uint32_t b[4];
                    uint32_t brow = (uint32_t)(((wn * 4 + jp) * 2 + (lane >> 4)) * 8 + (lane & 7));
                    uint32_t bcol = (uint32_t)(kk + (((lane >> 3) & 1) << 3));
                    ldsm4(b, sb + brow * 144 + bcol * 2);
                    mma_bf16(acc[0][2 * jp], a0, b);
                    mma_bf16(acc[0][2 * jp + 1], a0, b + 2);
                    mma_bf16(acc[1][2 * jp], a1, b);
                    mma_bf16(acc[1][2 * jp + 1], a1, b + 2);
                }
            }
        }
        // online logsumexp over this n-tile's 64 cols; 4 row-streams per thread
#pragma unroll
        for (int mi = 0; mi < 2; mi++) {
            float m0 = -1e30f, m1 = -1e30f;
#pragma unroll
            for (int j = 0; j < 8; j++) {
                m0 = fmaxf(m0, fmaxf(acc[mi][j][0], acc[mi][j][1]));
                m1 = fmaxf(m1, fmaxf(acc[mi][j][2], acc[mi][j][3]));
            }
            m0 = fmaxf(m0, __shfl_xor_sync(0xffffffffu, m0, 1));
            m0 = fmaxf(m0, __shfl_xor_sync(0xffffffffu, m0, 2));
            m1 = fmaxf(m1, __shfl_xor_sync(0xffffffffu, m1, 1));
            m1 = fmaxf(m1, __shfl_xor_sync(0xffffffffu, m1, 2));
            float nm0 = fmaxf(rm[mi * 2], m0), nm1 = fmaxf(rm[mi * 2 + 1], m1);
            float s0 = 0.f, s1 = 0.f;
#pragma unroll
            for (int j = 0; j < 8; j++) {
                s0 += __expf(acc[mi][j][0] - nm0) + __expf(acc[mi][j][1] - nm0);
                s1 += __expf(acc[mi][j][2] - nm1) + __expf(acc[mi][j][3] - nm1);
            }
            s0 += __shfl_xor_sync(0xffffffffu, s0, 1);
            s0 += __shfl_xor_sync(0xffffffffu, s0, 2);
            s1 += __shfl_xor_sync(0xffffffffu, s1, 1);
            s1 += __shfl_xor_sync(0xffffffffu, s1, 2);
            rs[mi * 2] = rs[mi * 2] * __expf(rm[mi * 2] - nm0) + s0;
            rs[mi * 2 + 1] = rs[mi * 2 + 1] * __expf(rm[mi * 2 + 1] - nm1) + s1;
            rm[mi * 2] = nm0;
            rm[mi * 2 + 1] = nm1;
        }
    }
    // combine the two col-half warps (wn=0/1) that own the same rows
    __syncthreads();
    float2* ex = (float2*)dsm;   // 128 entries, reuses stage buffers (compute done)
    int g = lane >> 2;
    if (wn == 1 && (lane & 3) == 0) {
#pragma unroll
        for (int k = 0; k < 4; k++) {
            float2 v; v.x = rm[k]; v.y = rs[k];
            ex[mbase + g + k * 8] = v;
        }
    }
    __syncthreads();
    if (wn == 0 && (lane & 3) == 0) {
#pragma unroll
        for (int k = 0; k < 4; k++) {
            int row = mbase + g + k * 8;
            float2 o = ex[row];
            float m = fmaxf(rm[k], o.x);
            float s = rs[k] * __expf(rm[k] - m) + o.y * __expf(o.x - m);
            g_pm[chunk * NTOK + tok0 + row] = m;
            g_ps[chunk * NTOK + tok0 + row] = s;
        }
    }
}

// ---------------- kernel 5: label logits ----------------
__global__ void __launch_bounds__(256) labeldot_kernel(const int* __restrict__ ids,
                                                       const int* __restrict__ mlab) {
    int tok = blockIdx.x * 8 + (threadIdx.x >> 5);
    int lane = threadIdx.x & 31;
    const __nv_bfloat16* x;
    int label;
    if (tok < 4096) {
        int b = tok >> 11, t = tok & 2047;
        if (t >= 2047) { if (!lane) g_ld[tok] = 0.f; return; }
        x = g_hid + (size_t)tok * HH;
        label = ids[b * SS + t + 1];
    } else {
        x = g_trans + (size_t)(tok - 4096) * HH;
        label = mlab[tok - 4096];
    }
    const __nv_bfloat162* x2 = (const __nv_bfloat162*)x;
    const __nv_bfloat162* w2 = (const __nv_bfloat162*)(g_Wbf + (size_t)label * HH);
    float acc = 0.f;
    for (int i = lane; i < HH / 2; i += 32) {
        float2 a = __bfloat1622float2(x2[i]);
        float2 b = __bfloat1622float2(w2[i]);
        acc += a.x * b.x + a.y * b.y;
    }
#pragma unroll
    for (int o = 16; o; o >>= 1) acc += __shfl_xor_sync(0xffffffffu, acc, o);
    if (!lane) g_ld[tok] = acc;
}

// ---------------- kernel 5b: combine 125 chunk partials -> per-token nll ----------------
__global__ void __launch_bounds__(256) nll_kernel() {
    int tok = blockIdx.x * 256 + threadIdx.x;
    if (tok >= NTOK) return;
    float m = -1e30f;
    for (int c = 0; c < NVC; c++) m = fmaxf(m, g_pm[c * NTOK + tok]);
    float s = 0.f;
    for (int c = 0; c < NVC; c++)
        s += g_ps[c * NTOK + tok] * __expf(g_pm[c * NTOK + tok] - m);
    g_nll[tok] = __logf(s) + m - g_ld[tok];
}

// ---------------- kernel 6: masked means ----------------
__global__ void __launch_bounds__(256) reduce_kernel(const int* __restrict__ starts,
                                                     const int* __restrict__ ends,
                                                     const int* __restrict__ attn,
                                                     const int* __restrict__ mmask,
                                                     float* __restrict__ out) {
    __shared__ int rl[2];
    __shared__ double red[6];
    int tid = threadIdx.x;
    if (tid < 2) rl[tid] = 0;
    if (tid < 6) red[tid] = 0.0;
    __syncthreads();
    int l0 = 0, l1 = 0;
    for (int i = tid; i < SS; i += 256) { l0 += attn[i]; l1 += attn[SS + i]; }
    atomicAdd(&rl[0], l0);
    atomicAdd(&rl[1], l1);
    __syncthreads();
    double s_st = 0, c_st = 0, s_fa = 0, c_fa = 0, s_m = 0, c_m = 0;
    for (int tok = tid; tok < NTOK; tok += 256) {
        float w_st = 0.f, w_fa = 0.f, w_m = 0.f;
        if (tok < 4096) {
            int b = tok >> 11, t = tok & 2047;
            if (t <= SS - 2) {
                if (t >= starts[b] - 1 && t <= ends[b] - 1) w_st = 1.f;
                if (t >= ends[b] && t < rl[b] - 1) w_fa = 1.f;
            }
        } else {
            if (mmask[tok - 4096]) w_m = 1.f;
        }
        if (w_st + w_fa + w_m > 0.f) {
            float nll = g_nll[tok];
            s_st += (double)(nll * w_st); c_st += w_st;
            s_fa += (double)(nll * w_fa); c_fa += w_fa;
            s_m  += (double)(nll * w_m);  c_m  += w_m;
        }
    }
    atomicAdd(&red[0], s_st); atomicAdd(&red[1], c_st);
    atomicAdd(&red[2], s_fa); atomicAdd(&red[3], c_fa);
    atomicAdd(&red[4], s_m);  atomicAdd(&red[5], c_m);
    __syncthreads();
    if (tid == 0) {
        double st = red[0] / fmax(red[1], 1.0);
        double fa = red[2] / fmax(red[3], 1.0);
        double ml = red[4] / fmax(red[5], 1.0);
        out[0] = (float)(0.5 * ml + 0.5 * st + 0.4 * fa);
        out[1] = (float)ml;
        out[2] = (float)st;
        out[3] = (float)fa;
    }
}

// ---------------- launch ----------------
extern "C" void kernel_launch(void* const* d_in, const int* in_sizes, int n_in,
                              void* d_out, int out_size) {
    const float* lhs    = (const float*)d_in[0];
    const int*   ids    = (const int*)d_in[1];
    const int*   attn   = (const int*)d_in[2];
    const int*   starts = (const int*)d_in[3];
    const int*   ends   = (const int*)d_in[4];
    const int*   mlab   = (const int*)d_in[5];
    const int*   mmask  = (const int*)d_in[6];
    const float* Am     = (const float*)d_in[8];
    const float* Bm     = (const float*)d_in[9];
    const float* bias   = (const float*)d_in[10];
    const float* W      = (const float*)d_in[11];
    float* out = (float*)d_out;

    cudaFuncSetAttribute(ce_kernel, cudaFuncAttributeMaxDynamicSharedMemorySize,
                         CE_SMEM_BYTES);

    convert_all<<<88576, 256>>>((const float4*)W, (const float4*)lhs,
                                (const float4*)Am, (const float4*)Bm);
    gemm1_kernel<<<32, 256>>>(starts);
    gemm2_kernel<<<256, 256>>>(bias);
    ce_kernel<<<dim3(48, NVC), 256, CE_SMEM_BYTES>>>(starts);
    labeldot_kernel<<<768, 256>>>(ids, mlab);
    nll_kernel<<<24, 256>>>();
    reduce_kernel<<<1, 256>>>(starts, ends, attn, mmask, out);
    (void)in_sizes; (void)n_in; (void)out_size;
}